// round 1
// baseline (speedup 1.0000x reference)
#include <cuda_runtime.h>
#include <math.h>

// Problem constants
#define RADIUS   512
#define DIAM     1024
#define N_WL     31
#define NPIX     (DIAM * DIAM)            // 1048576
#define NTOT     (NPIX * N_WL)            // 32505856

// Precomputed per-launch tables (device globals: no allocation allowed)
__device__ float g_table[RADIUS];   // quantized height table
__device__ float g_kdn[N_WL];       // k * delta_n per wavelength

// ---------------------------------------------------------------------------
// Init kernel: reproduce the jnp fp32 op chain EXACTLY (round-to-nearest each
// step, no contraction) so that downstream phase bits match the reference.
// ---------------------------------------------------------------------------
__global__ void doe_init_kernel(const float* __restrict__ hmw,
                                const float* __restrict__ wl)
{
    int t = threadIdx.x;

    if (t < RADIUS) {
        // q_base_height = lam0 / (refractive_index(lam0) - 1)
        const float lam0 = 7e-07f;
        float n0 = __fadd_rn(1.5f, __fdiv_rn(4e-15f, __fmul_rn(lam0, lam0)));
        float q  = __fdiv_rn(lam0, __fsub_rn(n0, 1.0f));
        // normed = (clip(w,-1,1)+1)*0.5 ; table = 0.002 - q*normed
        float x = fminf(fmaxf(hmw[t], -1.0f), 1.0f);
        float normed = __fmul_rn(__fadd_rn(x, 1.0f), 0.5f);
        g_table[t] = __fsub_rn(0.002f, __fmul_rn(q, normed));
    }
    if (t < N_WL) {
        float l  = wl[t];
        float dn = __fsub_rn(__fadd_rn(1.5f, __fdiv_rn(4e-15f, __fmul_rn(l, l))), 1.0f);
        float k  = __fdiv_rn(6.283185307179586f, l);  // fl32(2*pi)/wl
        g_kdn[t] = __fmul_rn(k, dn);
    }
}

// ---------------------------------------------------------------------------
// Main elementwise kernel: one thread per (pixel, wavelength) element.
// Big arrays (field_real/imag, out) are perfectly coalesced (wl innermost).
// ---------------------------------------------------------------------------
__global__ void __launch_bounds__(256)
doe_main_kernel(const float* __restrict__ fr,
                const float* __restrict__ fi,
                const float* __restrict__ noise,
                const float* __restrict__ rad,
                const float* __restrict__ ap,
                float* __restrict__ out)
{
    int i = blockIdx.x * blockDim.x + threadIdx.x;
    if (i >= NTOT) return;

    unsigned int ui = (unsigned int)i;
    unsigned int p  = ui / 31u;          // pixel index
    unsigned int w  = ui - p * 31u;      // wavelength index

    // --- hmap (fp32, exact op order matching reference) ---
    float r = rad[p];
    int idx = (int)ceilf(r) - 1;
    idx = min(max(idx, 0), RADIUS - 1);
    float hm = (r <= 512.0f) ? g_table[idx] : 0.0f;
    hm = __fadd_rn(hm, noise[p]);

    // --- phase in fp32 (bit-matching the reference's fp32 phase) ---
    float phase = __fmul_rn(g_kdn[w], hm);

    // --- accurate range reduction in double (phase up to ~1.7e4 rad) ---
    double pd = (double)phase;
    double nn = rint(pd * 0.15915494309189535);               // / (2*pi)
    float  rr = (float)fma(nn, -6.283185307179586, pd);       // exact residual

    float s, c;
    __sincosf(rr, &s, &c);   // |rr| <= pi : MUFU accurate to ~4e-7

    // --- complex rotate + aperture mask ---
    float a  = ap[p];
    float xr = fr[i];
    float xi = fi[i];

    out[i]        = (xr * c - xi * s) * a;
    out[NTOT + i] = (xr * s + xi * c) * a;
}

// ---------------------------------------------------------------------------
// kernel_launch: inputs in metadata order:
//   0 height_map_weight [512]
//   1 field_real  [1,1024,1024,31]
//   2 field_imag  [1,1024,1024,31]
//   3 wavelength  [31]
//   4 noise       [1,1024,1024,1]
//   5 radius_distance [1024,1024]
//   6 aperture    [1024,1024]
// output: [2,1,1024,1024,31] float32
// ---------------------------------------------------------------------------
extern "C" void kernel_launch(void* const* d_in, const int* in_sizes, int n_in,
                              void* d_out, int out_size)
{
    const float* hmw   = (const float*)d_in[0];
    const float* fr    = (const float*)d_in[1];
    const float* fi    = (const float*)d_in[2];
    const float* wl    = (const float*)d_in[3];
    const float* noise = (const float*)d_in[4];
    const float* rad   = (const float*)d_in[5];
    const float* ap    = (const float*)d_in[6];
    float* out = (float*)d_out;

    doe_init_kernel<<<1, RADIUS>>>(hmw, wl);

    const int threads = 256;
    const int blocks  = (NTOT + threads - 1) / threads;   // 126976
    doe_main_kernel<<<blocks, threads>>>(fr, fi, noise, rad, ap, out);
}

// round 2
// speedup vs baseline: 1.8492x; 1.8492x over previous
#include <cuda_runtime.h>
#include <math.h>

// Problem constants
#define RADIUS   512
#define DIAM     1024
#define N_WL     31
#define NPIX     (DIAM * DIAM)            // 1048576
#define NTOT     (NPIX * N_WL)            // 32505856

// Precomputed per-launch tables (device globals: no allocation allowed)
__device__ float g_table[RADIUS];   // quantized height table
__device__ float g_kdn[N_WL];       // k * delta_n per wavelength

// ---------------------------------------------------------------------------
// Init kernel: reproduce the jnp fp32 op chain EXACTLY (round-to-nearest each
// step, no contraction) so that downstream phase bits match the reference.
// ---------------------------------------------------------------------------
__global__ void doe_init_kernel(const float* __restrict__ hmw,
                                const float* __restrict__ wl)
{
    int t = threadIdx.x;

    if (t < RADIUS) {
        // q_base_height = lam0 / (refractive_index(lam0) - 1)
        const float lam0 = 7e-07f;
        float n0 = __fadd_rn(1.5f, __fdiv_rn(4e-15f, __fmul_rn(lam0, lam0)));
        float q  = __fdiv_rn(lam0, __fsub_rn(n0, 1.0f));
        // normed = (clip(w,-1,1)+1)*0.5 ; table = 0.002 - q*normed
        float x = fminf(fmaxf(hmw[t], -1.0f), 1.0f);
        float normed = __fmul_rn(__fadd_rn(x, 1.0f), 0.5f);
        g_table[t] = __fsub_rn(0.002f, __fmul_rn(q, normed));
    }
    if (t < N_WL) {
        float l  = wl[t];
        float dn = __fsub_rn(__fadd_rn(1.5f, __fdiv_rn(4e-15f, __fmul_rn(l, l))), 1.0f);
        float k  = __fdiv_rn(6.283185307179586f, l);  // fl32(2*pi)/wl
        g_kdn[t] = __fmul_rn(k, dn);
    }
}

// ---------------------------------------------------------------------------
// Main elementwise kernel: one thread per (pixel, wavelength) element.
// Big arrays (field_real/imag, out) are perfectly coalesced (wl innermost).
// Pure fp32 path: NO FP64 anywhere (GB300 FP64 pipe is ~2 lanes/cyc/SM and
// was the R1 bottleneck).
// ---------------------------------------------------------------------------
__global__ void __launch_bounds__(256)
doe_main_kernel(const float* __restrict__ fr,
                const float* __restrict__ fi,
                const float* __restrict__ noise,
                const float* __restrict__ rad,
                const float* __restrict__ ap,
                float* __restrict__ out)
{
    int i = blockIdx.x * blockDim.x + threadIdx.x;
    if (i >= NTOT) return;

    unsigned int ui = (unsigned int)i;
    unsigned int p  = ui / 31u;          // pixel index (magic-multiply, cheap)
    unsigned int w  = ui - p * 31u;      // wavelength index

    // Issue the streaming loads early (independent of the math below)
    float xr = fr[i];
    float xi = fi[i];

    // --- hmap (fp32, exact op order matching reference) ---
    float r = rad[p];
    int idx = (int)ceilf(r) - 1;
    idx = min(max(idx, 0), RADIUS - 1);
    float hm = (r <= 512.0f) ? g_table[idx] : 0.0f;
    hm = __fadd_rn(hm, noise[p]);

    // --- phase in fp32 (bit-matching the reference's fp32 phase) ---
    float phase = __fmul_rn(g_kdn[w], hm);

    // --- fp32 Cody-Waite range reduction (2-term, FMA-based) ---
    // 2*pi = PI2_HI + PI2_LO ; n <= ~2630 exact in fp32.
    const float INV2PI = 0.15915494309189535f;
    const float PI2_HI = 6.28318548202514648f;   // fl32(2*pi)
    const float PI2_LO = -1.74845553146957e-7f;  // 2*pi - PI2_HI
    float nf = rintf(__fmul_rn(phase, INV2PI));
    float rr = fmaf(-nf, PI2_HI, phase);         // exact product, 1 rounding
    rr = fmaf(-nf, PI2_LO, rr);                  // |rr| <= pi + tiny

    float s, c;
    __sincosf(rr, &s, &c);   // MUFU, abs err ~3e-7 on [-pi,pi]

    // --- complex rotate + aperture mask ---
    float a = ap[p];
    out[i]        = (xr * c - xi * s) * a;
    out[NTOT + i] = (xr * s + xi * c) * a;
}

// ---------------------------------------------------------------------------
// kernel_launch: inputs in metadata order:
//   0 height_map_weight [512]
//   1 field_real  [1,1024,1024,31]
//   2 field_imag  [1,1024,1024,31]
//   3 wavelength  [31]
//   4 noise       [1,1024,1024,1]
//   5 radius_distance [1024,1024]
//   6 aperture    [1024,1024]
// output: [2,1,1024,1024,31] float32
// ---------------------------------------------------------------------------
extern "C" void kernel_launch(void* const* d_in, const int* in_sizes, int n_in,
                              void* d_out, int out_size)
{
    const float* hmw   = (const float*)d_in[0];
    const float* fr    = (const float*)d_in[1];
    const float* fi    = (const float*)d_in[2];
    const float* wl    = (const float*)d_in[3];
    const float* noise = (const float*)d_in[4];
    const float* rad   = (const float*)d_in[5];
    const float* ap    = (const float*)d_in[6];
    float* out = (float*)d_out;

    doe_init_kernel<<<1, RADIUS>>>(hmw, wl);

    const int threads = 256;
    const int blocks  = (NTOT + threads - 1) / threads;   // 126976
    doe_main_kernel<<<blocks, threads>>>(fr, fi, noise, rad, ap, out);
}

// round 3
// speedup vs baseline: 3.5210x; 1.9041x over previous
#include <cuda_runtime.h>
#include <math.h>

// Problem constants
#define RADIUS   512
#define DIAM     1024
#define N_WL     31
#define NPIX     (DIAM * DIAM)            // 1048576
#define NTOT     (NPIX * N_WL)            // 32505856
#define NVEC     (NTOT / 4)               // 8126464 float4 groups

// Precomputed tables / per-pixel data (device globals: no allocation allowed)
__device__ float  g_table[RADIUS];        // quantized height table
__device__ float  g_kdn[N_WL];            // k * delta_n per wavelength
__device__ float2 g_pix[NPIX];            // (hmap + noise, aperture) per pixel

// ---------------------------------------------------------------------------
// Init kernel: reproduce the jnp fp32 op chain EXACTLY (round-to-nearest each
// step, no contraction) so that downstream phase bits match the reference.
// ---------------------------------------------------------------------------
__global__ void doe_init_kernel(const float* __restrict__ hmw,
                                const float* __restrict__ wl)
{
    int t = threadIdx.x;

    if (t < RADIUS) {
        const float lam0 = 7e-07f;
        float n0 = __fadd_rn(1.5f, __fdiv_rn(4e-15f, __fmul_rn(lam0, lam0)));
        float q  = __fdiv_rn(lam0, __fsub_rn(n0, 1.0f));
        float x = fminf(fmaxf(hmw[t], -1.0f), 1.0f);
        float normed = __fmul_rn(__fadd_rn(x, 1.0f), 0.5f);
        g_table[t] = __fsub_rn(0.002f, __fmul_rn(q, normed));
    }
    if (t < N_WL) {
        float l  = wl[t];
        float dn = __fsub_rn(__fadd_rn(1.5f, __fdiv_rn(4e-15f, __fmul_rn(l, l))), 1.0f);
        float k  = __fdiv_rn(6.283185307179586f, l);
        g_kdn[t] = __fmul_rn(k, dn);
    }
}

// ---------------------------------------------------------------------------
// Per-pixel precompute: hmap (+noise) and aperture, packed as float2.
// Exact fp32 op order matching the reference.
// ---------------------------------------------------------------------------
__global__ void __launch_bounds__(256)
doe_pix_kernel(const float* __restrict__ noise,
               const float* __restrict__ rad,
               const float* __restrict__ ap)
{
    int p = blockIdx.x * blockDim.x + threadIdx.x;
    if (p >= NPIX) return;

    float r = rad[p];
    int idx = (int)ceilf(r) - 1;
    idx = min(max(idx, 0), RADIUS - 1);
    float hm = (r <= 512.0f) ? g_table[idx] : 0.0f;
    hm = __fadd_rn(hm, noise[p]);

    g_pix[p] = make_float2(hm, ap[p]);
}

// ---------------------------------------------------------------------------
// Main kernel: one thread per 4 consecutive (pixel,wl) elements. Stream is
// float4-vectorized; a 4-group touches at most 2 pixels (broadcast L1 hits).
// ---------------------------------------------------------------------------
__global__ void __launch_bounds__(256)
doe_main_kernel(const float4* __restrict__ fr,
                const float4* __restrict__ fi,
                float4* __restrict__ out)
{
    int t = blockIdx.x * blockDim.x + threadIdx.x;
    if (t >= NVEC) return;

    unsigned int base = (unsigned int)t * 4u;
    unsigned int p0 = base / 31u;                 // magic-multiply
    unsigned int w0 = base - p0 * 31u;

    // Streaming loads (don't pollute caches needed by broadcast data)
    float4 vr = __ldcs(&fr[t]);
    float4 vi = __ldcs(&fi[t]);

    // Pixel data for p0 and (possible) successor
    float2 pixA = g_pix[p0];
    unsigned int p1 = (p0 + 1u < NPIX) ? p0 + 1u : p0;
    float2 pixB = g_pix[p1];

    const float INV2PI = 0.15915494309189535f;
    const float PI2_HI = 6.28318548202514648f;    // fl32(2*pi)
    const float PI2_LO = -1.74845553146957e-7f;   // 2*pi - fl32(2*pi)

    float oR[4], oI[4];
    float xr4[4] = {vr.x, vr.y, vr.z, vr.w};
    float xi4[4] = {vi.x, vi.y, vi.z, vi.w};

#pragma unroll
    for (int j = 0; j < 4; j++) {
        unsigned int w = w0 + j;
        bool wrap = (w >= N_WL);
        unsigned int wr = wrap ? w - N_WL : w;
        float hm = wrap ? pixB.x : pixA.x;
        float a  = wrap ? pixB.y : pixA.y;

        // phase in fp32 (bit-matching the reference's fp32 phase)
        float phase = __fmul_rn(g_kdn[wr], hm);

        // fp32 Cody-Waite range reduction (2-term, FMA-based)
        float nf = rintf(__fmul_rn(phase, INV2PI));
        float rr = fmaf(-nf, PI2_HI, phase);
        rr = fmaf(-nf, PI2_LO, rr);

        float s, c;
        __sincosf(rr, &s, &c);

        float xr = xr4[j], xi = xi4[j];
        oR[j] = (xr * c - xi * s) * a;
        oI[j] = (xr * s + xi * c) * a;
    }

    __stcs(&out[t],        make_float4(oR[0], oR[1], oR[2], oR[3]));
    __stcs(&out[NVEC + t], make_float4(oI[0], oI[1], oI[2], oI[3]));
}

// ---------------------------------------------------------------------------
// kernel_launch: inputs in metadata order:
//   0 height_map_weight [512]
//   1 field_real  [1,1024,1024,31]
//   2 field_imag  [1,1024,1024,31]
//   3 wavelength  [31]
//   4 noise       [1,1024,1024,1]
//   5 radius_distance [1024,1024]
//   6 aperture    [1024,1024]
// output: [2,1,1024,1024,31] float32
// ---------------------------------------------------------------------------
extern "C" void kernel_launch(void* const* d_in, const int* in_sizes, int n_in,
                              void* d_out, int out_size)
{
    const float* hmw   = (const float*)d_in[0];
    const float* fr    = (const float*)d_in[1];
    const float* fi    = (const float*)d_in[2];
    const float* wl    = (const float*)d_in[3];
    const float* noise = (const float*)d_in[4];
    const float* rad   = (const float*)d_in[5];
    const float* ap    = (const float*)d_in[6];
    float* out = (float*)d_out;

    doe_init_kernel<<<1, RADIUS>>>(hmw, wl);
    doe_pix_kernel<<<(NPIX + 255) / 256, 256>>>(noise, rad, ap);

    const int threads = 256;
    const int blocks  = (NVEC + threads - 1) / threads;   // 31744
    doe_main_kernel<<<blocks, threads>>>((const float4*)fr,
                                         (const float4*)fi,
                                         (float4*)out);
}

// round 4
// speedup vs baseline: 3.6755x; 1.0439x over previous
#include <cuda_runtime.h>
#include <math.h>

// Problem constants
#define RADIUS   512
#define DIAM     1024
#define N_WL     31
#define NPIX     (DIAM * DIAM)            // 1048576
#define NTOT     (NPIX * N_WL)            // 32505856
#define NVEC     (NTOT / 4)               // 8126464 float4 groups
#define NPIX4    (NPIX / 4)               // 262144

// Precomputed tables / per-pixel data (device globals: no allocation allowed)
__device__ float  g_kdn[N_WL];            // k * delta_n per wavelength
__device__ float2 g_pix[NPIX];            // (hmap + noise, aperture) per pixel

// ---------------------------------------------------------------------------
// Single fused prologue kernel:
//  - each thread handles 4 pixels (vectorized loads/stores), computing the
//    quantized-height-table entry INLINE (exact fp32 op chain of reference)
//  - the first 31 threads also compute g_kdn (exact fp32 op chain)
// ---------------------------------------------------------------------------
__global__ void __launch_bounds__(256)
doe_pre_kernel(const float* __restrict__ hmw,
               const float* __restrict__ wl,
               const float4* __restrict__ noise4,
               const float4* __restrict__ rad4,
               const float4* __restrict__ ap4)
{
    int t = blockIdx.x * blockDim.x + threadIdx.x;

    if (t < N_WL) {
        float l  = wl[t];
        float dn = __fsub_rn(__fadd_rn(1.5f, __fdiv_rn(4e-15f, __fmul_rn(l, l))), 1.0f);
        float k  = __fdiv_rn(6.283185307179586f, l);
        g_kdn[t] = __fmul_rn(k, dn);
    }

    if (t >= NPIX4) return;

    // q_base_height (same fp32 intrinsic chain as reference; constant-folds)
    const float lam0 = 7e-07f;
    float n0 = __fadd_rn(1.5f, __fdiv_rn(4e-15f, __fmul_rn(lam0, lam0)));
    float q  = __fdiv_rn(lam0, __fsub_rn(n0, 1.0f));

    float4 r4 = rad4[t];
    float4 n4 = noise4[t];
    float4 a4 = ap4[t];

    float rr[4] = {r4.x, r4.y, r4.z, r4.w};
    float nn[4] = {n4.x, n4.y, n4.z, n4.w};
    float aa[4] = {a4.x, a4.y, a4.z, a4.w};

    float2 px[4];
#pragma unroll
    for (int j = 0; j < 4; j++) {
        float r = rr[j];
        int idx = (int)ceilf(r) - 1;
        idx = min(max(idx, 0), RADIUS - 1);
        // table entry inline: 0.002 - q * ((clip(w,-1,1)+1)*0.5)
        float x = fminf(fmaxf(__ldg(&hmw[idx]), -1.0f), 1.0f);
        float normed = __fmul_rn(__fadd_rn(x, 1.0f), 0.5f);
        float tb = __fsub_rn(0.002f, __fmul_rn(q, normed));
        float hm = (r <= 512.0f) ? tb : 0.0f;
        hm = __fadd_rn(hm, nn[j]);
        px[j] = make_float2(hm, aa[j]);
    }

    // two float4 stores = 4 float2 pixel records
    float4* dst = (float4*)&g_pix[t * 4];
    dst[0] = make_float4(px[0].x, px[0].y, px[1].x, px[1].y);
    dst[1] = make_float4(px[2].x, px[2].y, px[3].x, px[3].y);
}

// ---------------------------------------------------------------------------
// Main kernel: one thread per 4 consecutive (pixel,wl) elements. Stream is
// float4-vectorized; a 4-group touches at most 2 pixels (broadcast L1 hits).
// (Unchanged from R3 — it runs at ~87% of HBM spec.)
// ---------------------------------------------------------------------------
__global__ void __launch_bounds__(256)
doe_main_kernel(const float4* __restrict__ fr,
                const float4* __restrict__ fi,
                float4* __restrict__ out)
{
    int t = blockIdx.x * blockDim.x + threadIdx.x;
    if (t >= NVEC) return;

    unsigned int base = (unsigned int)t * 4u;
    unsigned int p0 = base / 31u;                 // magic-multiply
    unsigned int w0 = base - p0 * 31u;

    // Streaming loads (don't pollute caches needed by broadcast data)
    float4 vr = __ldcs(&fr[t]);
    float4 vi = __ldcs(&fi[t]);

    // Pixel data for p0 and (possible) successor
    float2 pixA = g_pix[p0];
    unsigned int p1 = (p0 + 1u < NPIX) ? p0 + 1u : p0;
    float2 pixB = g_pix[p1];

    const float INV2PI = 0.15915494309189535f;
    const float PI2_HI = 6.28318548202514648f;    // fl32(2*pi)
    const float PI2_LO = -1.74845553146957e-7f;   // 2*pi - fl32(2*pi)

    float oR[4], oI[4];
    float xr4[4] = {vr.x, vr.y, vr.z, vr.w};
    float xi4[4] = {vi.x, vi.y, vi.z, vi.w};

#pragma unroll
    for (int j = 0; j < 4; j++) {
        unsigned int w = w0 + j;
        bool wrap = (w >= N_WL);
        unsigned int wr = wrap ? w - N_WL : w;
        float hm = wrap ? pixB.x : pixA.x;
        float a  = wrap ? pixB.y : pixA.y;

        // phase in fp32 (bit-matching the reference's fp32 phase)
        float phase = __fmul_rn(g_kdn[wr], hm);

        // fp32 Cody-Waite range reduction (2-term, FMA-based)
        float nf = rintf(__fmul_rn(phase, INV2PI));
        float rr = fmaf(-nf, PI2_HI, phase);
        rr = fmaf(-nf, PI2_LO, rr);

        float s, c;
        __sincosf(rr, &s, &c);

        float xr = xr4[j], xi = xi4[j];
        oR[j] = (xr * c - xi * s) * a;
        oI[j] = (xr * s + xi * c) * a;
    }

    __stcs(&out[t],        make_float4(oR[0], oR[1], oR[2], oR[3]));
    __stcs(&out[NVEC + t], make_float4(oI[0], oI[1], oI[2], oI[3]));
}

// ---------------------------------------------------------------------------
// kernel_launch: inputs in metadata order:
//   0 height_map_weight [512]
//   1 field_real  [1,1024,1024,31]
//   2 field_imag  [1,1024,1024,31]
//   3 wavelength  [31]
//   4 noise       [1,1024,1024,1]
//   5 radius_distance [1024,1024]
//   6 aperture    [1024,1024]
// output: [2,1,1024,1024,31] float32
// ---------------------------------------------------------------------------
extern "C" void kernel_launch(void* const* d_in, const int* in_sizes, int n_in,
                              void* d_out, int out_size)
{
    const float* hmw   = (const float*)d_in[0];
    const float* fr    = (const float*)d_in[1];
    const float* fi    = (const float*)d_in[2];
    const float* wl    = (const float*)d_in[3];
    const float* noise = (const float*)d_in[4];
    const float* rad   = (const float*)d_in[5];
    const float* ap    = (const float*)d_in[6];
    float* out = (float*)d_out;

    doe_pre_kernel<<<(NPIX4 + 255) / 256, 256>>>(hmw, wl,
                                                 (const float4*)noise,
                                                 (const float4*)rad,
                                                 (const float4*)ap);

    const int threads = 256;
    const int blocks  = (NVEC + threads - 1) / threads;   // 31744
    doe_main_kernel<<<blocks, threads>>>((const float4*)fr,
                                         (const float4*)fi,
                                         (float4*)out);
}

// round 5
// speedup vs baseline: 3.6970x; 1.0059x over previous
#include <cuda_runtime.h>
#include <math.h>

// Problem constants
#define RADIUS   512
#define DIAM     1024
#define N_WL     31
#define NPIX     (DIAM * DIAM)            // 1048576
#define NTOT     (NPIX * N_WL)            // 32505856
#define NVEC     (NTOT / 4)               // 8126464 float4 groups

// ---------------------------------------------------------------------------
// Fully fused kernel: one thread per 4 consecutive (pixel,wl) elements.
//  - k*delta_n table rebuilt per block in shared memory (31 divides, trivial)
//  - per-pixel height map computed inline (exact fp32 op chain of reference)
//  - stream float4-vectorized with streaming cache hints
// ---------------------------------------------------------------------------
__global__ void __launch_bounds__(256)
doe_fused_kernel(const float4* __restrict__ fr,
                 const float4* __restrict__ fi,
                 const float*  __restrict__ hmw,
                 const float*  __restrict__ wl,
                 const float*  __restrict__ noise,
                 const float*  __restrict__ rad,
                 const float*  __restrict__ ap,
                 float4* __restrict__ out)
{
    __shared__ float s_kdn[N_WL];
    if (threadIdx.x < N_WL) {
        float l  = __ldg(&wl[threadIdx.x]);
        float dn = __fsub_rn(__fadd_rn(1.5f, __fdiv_rn(4e-15f, __fmul_rn(l, l))), 1.0f);
        float k  = __fdiv_rn(6.283185307179586f, l);
        s_kdn[threadIdx.x] = __fmul_rn(k, dn);
    }
    __syncthreads();

    int t = blockIdx.x * blockDim.x + threadIdx.x;
    if (t >= NVEC) return;

    unsigned int base = (unsigned int)t * 4u;
    unsigned int p0 = base / 31u;                 // magic-multiply
    unsigned int w0 = base - p0 * 31u;
    unsigned int p1 = (p0 + 1u < NPIX) ? p0 + 1u : p0;

    // Streaming loads (issued early; don't pollute caches for broadcast data)
    float4 vr = __ldcs(&fr[t]);
    float4 vi = __ldcs(&fi[t]);

    // q_base_height: same fp32 intrinsic chain as reference (constant-folds)
    const float lam0 = 7e-07f;
    float n0 = __fadd_rn(1.5f, __fdiv_rn(4e-15f, __fmul_rn(lam0, lam0)));
    float q  = __fdiv_rn(lam0, __fsub_rn(n0, 1.0f));

    // Inline per-pixel (hmap+noise, aperture) for p0 and p1.
    float hmA, apA, hmB, apB;
    {
        float r = __ldg(&rad[p0]);
        int idx = (int)ceilf(r) - 1;
        idx = min(max(idx, 0), RADIUS - 1);
        float x = fminf(fmaxf(__ldg(&hmw[idx]), -1.0f), 1.0f);
        float normed = __fmul_rn(__fadd_rn(x, 1.0f), 0.5f);
        float tb = __fsub_rn(0.002f, __fmul_rn(q, normed));
        float hm = (r <= 512.0f) ? tb : 0.0f;
        hmA = __fadd_rn(hm, __ldg(&noise[p0]));
        apA = __ldg(&ap[p0]);
    }
    {
        float r = __ldg(&rad[p1]);
        int idx = (int)ceilf(r) - 1;
        idx = min(max(idx, 0), RADIUS - 1);
        float x = fminf(fmaxf(__ldg(&hmw[idx]), -1.0f), 1.0f);
        float normed = __fmul_rn(__fadd_rn(x, 1.0f), 0.5f);
        float tb = __fsub_rn(0.002f, __fmul_rn(q, normed));
        float hm = (r <= 512.0f) ? tb : 0.0f;
        hmB = __fadd_rn(hm, __ldg(&noise[p1]));
        apB = __ldg(&ap[p1]);
    }

    const float INV2PI = 0.15915494309189535f;
    const float PI2_HI = 6.28318548202514648f;    // fl32(2*pi)
    const float PI2_LO = -1.74845553146957e-7f;   // 2*pi - fl32(2*pi)

    float oR[4], oI[4];
    float xr4[4] = {vr.x, vr.y, vr.z, vr.w};
    float xi4[4] = {vi.x, vi.y, vi.z, vi.w};

#pragma unroll
    for (int j = 0; j < 4; j++) {
        unsigned int w = w0 + j;
        bool wrap = (w >= N_WL);
        unsigned int wr = wrap ? w - N_WL : w;
        float hm = wrap ? hmB : hmA;
        float a  = wrap ? apB : apA;

        // phase in fp32 (bit-matching the reference's fp32 phase)
        float phase = __fmul_rn(s_kdn[wr], hm);

        // fp32 Cody-Waite range reduction (2-term, FMA-based)
        float nf = rintf(__fmul_rn(phase, INV2PI));
        float rr = fmaf(-nf, PI2_HI, phase);
        rr = fmaf(-nf, PI2_LO, rr);

        float s, c;
        __sincosf(rr, &s, &c);

        float xr = xr4[j], xi = xi4[j];
        oR[j] = (xr * c - xi * s) * a;
        oI[j] = (xr * s + xi * c) * a;
    }

    __stcs(&out[t],        make_float4(oR[0], oR[1], oR[2], oR[3]));
    __stcs(&out[NVEC + t], make_float4(oI[0], oI[1], oI[2], oI[3]));
}

// ---------------------------------------------------------------------------
// kernel_launch: inputs in metadata order:
//   0 height_map_weight [512]
//   1 field_real  [1,1024,1024,31]
//   2 field_imag  [1,1024,1024,31]
//   3 wavelength  [31]
//   4 noise       [1,1024,1024,1]
//   5 radius_distance [1024,1024]
//   6 aperture    [1024,1024]
// output: [2,1,1024,1024,31] float32
// ---------------------------------------------------------------------------
extern "C" void kernel_launch(void* const* d_in, const int* in_sizes, int n_in,
                              void* d_out, int out_size)
{
    const float* hmw   = (const float*)d_in[0];
    const float* fr    = (const float*)d_in[1];
    const float* fi    = (const float*)d_in[2];
    const float* wl    = (const float*)d_in[3];
    const float* noise = (const float*)d_in[4];
    const float* rad   = (const float*)d_in[5];
    const float* ap    = (const float*)d_in[6];
    float* out = (float*)d_out;

    const int threads = 256;
    const int blocks  = (NVEC + threads - 1) / threads;   // 31744
    doe_fused_kernel<<<blocks, threads>>>((const float4*)fr,
                                          (const float4*)fi,
                                          hmw, wl, noise, rad, ap,
                                          (float4*)out);
}